// round 17
// baseline (speedup 1.0000x reference)
#include <cuda_runtime.h>
#include <cuda_pipeline.h>
#include <math.h>

#define BNUM 32
#define SEQ  2048
#define DIM  1024
#define HID  512
#define NTOK (BNUM * SEQ)   // 65536
#define MARGIN 20.0f        // dropped alpha mass < 2048*exp(-20) ~ 4e-6 << 1e-3 tol

// ---------------- scratch (alignment under our control) ----------------
__device__ __align__(256) float d_H[(size_t)NTOK * HID];
__device__ __align__(256) float d_qk[DIM];
__device__ float d_xq[NTOK];
__device__ float d_g[NTOK];
__device__ float d_dec[NTOK];
__device__ int   d_len[BNUM];
__device__ int   d_idx[NTOK];
__device__ int   d_cnt;
__device__ int   d_rowcnt[BNUM];
__device__ int   d_c0a[16];
__device__ int   d_c3a[16];

// ---------------- helpers ----------------
__device__ __forceinline__ float warp_red(float v, bool domax) {
    #pragma unroll
    for (int o = 16; o; o >>= 1) {
        float ov = __shfl_xor_sync(0xffffffffu, v, o);
        v = domax ? fmaxf(v, ov) : (v + ov);
    }
    return v;
}
__device__ __forceinline__ float blk_reduce256(float v, float* red, bool domax) {
    v = warp_red(v, domax);
    int w = threadIdx.x >> 5;
    if ((threadIdx.x & 31) == 0) red[w] = v;
    __syncthreads();
    float r = (threadIdx.x < 8) ? red[threadIdx.x] : (domax ? -1e30f : 0.0f);
    if (threadIdx.x < 32) {
        #pragma unroll
        for (int o = 4; o; o >>= 1) {
            float orr = __shfl_xor_sync(0xffffffffu, r, o);
            r = domax ? fmaxf(r, orr) : (r + orr);
        }
        if (threadIdx.x == 0) red[0] = r;
    }
    __syncthreads();
    float out = red[0];
    __syncthreads();
    return out;
}
__device__ __forceinline__ float blk_reduce128(float v, float* red, bool domax) {
    v = warp_red(v, domax);
    int w = threadIdx.x >> 5;
    if ((threadIdx.x & 31) == 0) red[w] = v;
    __syncthreads();
    if (threadIdx.x < 32) {
        float r = (threadIdx.x < 4) ? red[threadIdx.x] : (domax ? -1e30f : 0.0f);
        #pragma unroll
        for (int o = 2; o; o >>= 1) {
            float orr = __shfl_xor_sync(0xffffffffu, r, o);
            r = domax ? fmaxf(r, orr) : (r + orr);
        }
        if (threadIdx.x == 0) red[0] = r;
    }
    __syncthreads();
    float out = red[0];
    __syncthreads();
    return out;
}

// ---------------- k0d: mask dtype detect (16 blocks, byte loads) + counter init ------
// Reads first 65536 bytes bytewise (in-bounds for u8/i32/f32 mask).
// i32 0/1 LE: nonzero bytes only at p%4==0. f32 1.0f LE: only p%4 in {2,3}. u8: mixed.
__global__ void k0d(const unsigned char* __restrict__ mb) {
    int tid = threadIdx.x;
    __shared__ int c0s, c3s;
    if (tid == 0) { c0s = 0; c3s = 0; if (blockIdx.x == 0) d_cnt = 0; }
    if (blockIdx.x == 0 && tid < BNUM) d_rowcnt[tid] = 0;
    __syncthreads();
    const unsigned char* p = mb + blockIdx.x * 4096 + tid * 16;
    int c0 = 0, c3 = 0;
    #pragma unroll
    for (int i = 0; i < 16; i++) {
        unsigned char v = p[i];
        int pos = (tid * 16 + i) & 3;
        if (v) { if (pos == 0) c0++; else if (pos == 3) c3++; }
    }
    #pragma unroll
    for (int o = 16; o; o >>= 1) {
        c0 += __shfl_xor_sync(0xffffffffu, c0, o);
        c3 += __shfl_xor_sync(0xffffffffu, c3, o);
    }
    if ((tid & 31) == 0) { atomicAdd(&c0s, c0); atomicAdd(&c3s, c3); }
    __syncthreads();
    if (tid == 0) { d_c0a[blockIdx.x] = c0s; d_c3a[blockIdx.x] = c3s; }
}

// dtype decision from detect partials: 0=u8, 1=int32, 2=float32
__device__ __forceinline__ int mask_dtype() {
    int c0 = 0, c3 = 0;
    #pragma unroll
    for (int i = 0; i < 16; i++) { c0 += d_c0a[i]; c3 += d_c3a[i]; }
    if (c0 > 0 && c3 == 0) return 1;
    if (c0 == 0 && c3 > 0) return 2;
    return 0;
}

// ---------------- kA: blocks 0..31 = len, blocks 32.. = qk (scalar loads) ------------
__global__ void kA(const void* __restrict__ mask,
                   const float* __restrict__ kw, const float* __restrict__ q) {
    int tid = threadIdx.x;
    if (blockIdx.x < 32) {
        int b = blockIdx.x;
        __shared__ int cs;
        if (tid == 0) cs = 0;
        __syncthreads();
        int c = 0, f = mask_dtype();
        if (f == 0) {
            const unsigned char* m = (const unsigned char*)mask + b * SEQ;
            #pragma unroll
            for (int i = 0; i < 8; i++) c += (m[tid + i * 256] != 0);
        } else {
            const unsigned int* m = (const unsigned int*)mask + b * SEQ;
            #pragma unroll
            for (int i = 0; i < 8; i++) c += (m[tid + i * 256] != 0u);
        }
        atomicAdd(&cs, c);
        __syncthreads();
        if (tid == 0) d_len[b] = SEQ - cs;
    } else {
        __shared__ float red[8];
        int d = blockIdx.x - 32;
        const float* row = kw + (size_t)d * DIM;
        float s = 0.0f;
        #pragma unroll
        for (int i = 0; i < 4; i++) {          // scalar, warp-contiguous
            int e = tid + i * 256;
            s += row[e] * q[e];
        }
        s = blk_reduce256(s, red, false);
        if (tid == 0) d_qk[d] = s;
    }
}

// ---------------- kB: xq (+ fused per-row selection by last-arriving block) ----------
// g in (0,1) => g*xq in [min(xq,0), max(xq,0)]. Select s iff upper >= max lower - MARGIN.
__global__ void kB(const float* __restrict__ X, const float* __restrict__ dlam) {
    __shared__ float qs[DIM];
    __shared__ float red[8];
    __shared__ int islast;
    int blk = blockIdx.x;                 // 4096 blocks, 16 tokens each
    int b = blk >> 7;                     // 128 blocks per batch row
    int s_start = (blk & 127) << 4;
    int tid = threadIdx.x;
    int L = d_len[b];

    if (s_start < L) {                    // fully-padded blocks skip the xq work
        for (int i = tid; i < DIM; i += 256) qs[i] = d_qk[i];
        __syncthreads();
        int w = tid >> 5, lane = tid & 31;
        int t0 = blk * 16 + w;            // warp handles t0 and t0+8
        const float* x0 = X + (size_t)t0 * DIM;
        const float* x1 = x0 + (size_t)8 * DIM;
        float s0 = 0.0f, s1 = 0.0f;
        #pragma unroll
        for (int i = 0; i < 32; i++) {    // scalar, warp-contiguous per instr
            int e = lane + i * 32;
            float bq = qs[e];
            s0 += x0[e] * bq;
            s1 += x1[e] * bq;
        }
        s0 = warp_red(s0, false);
        s1 = warp_red(s1, false);
        if (lane == 0) { d_xq[t0] = s0; d_xq[t0 + 8] = s1; }
    }
    __syncthreads();
    if (tid == 0) {
        __threadfence();                  // publish d_xq before counter bump
        int old = atomicAdd(&d_rowcnt[b], 1);
        islast = (old == 127);
    }
    __syncthreads();
    if (!islast) return;

    // --- selection for row b (this is the 128th/last block of the row) ---
    float lam = log1pf(expf(dlam[0]));
    float lmax = -1e30f;
    for (int s = tid; s < SEQ; s += 256) {
        if (s < L) {
            float xq = d_xq[b * SEQ + s];
            float l = fminf(xq, 0.0f) * 0.03125f - lam * (float)(L - 1 - s);
            lmax = fmaxf(lmax, l);
        }
    }
    lmax = blk_reduce256(lmax, red, true);
    float thr = lmax - MARGIN;
    for (int s = tid; s < SEQ; s += 256) {
        int t = b * SEQ + s;
        d_dec[t] = -1e30f;
        if (s < L) {
            float xq = d_xq[t];
            float u = fmaxf(xq, 0.0f) * 0.03125f - lam * (float)(L - 1 - s);
            if (u >= thr) { int p = atomicAdd(&d_cnt, 1); d_idx[p] = t; }
        }
    }
}

// ---------------- kD: gathered GEMM  H = GELU(X[sel] @ W1 + b1) ----------------
// 4-stage async-copy pipeline via <cuda_pipeline.h> intrinsics (4B copies:
// no input-alignment assumption beyond the natural 4B of float).
#define BM 32
#define BN 64
#define BK 16
#define STG 4
__global__ __launch_bounds__(128) void kD(const float* __restrict__ X,
                                          const float* __restrict__ W1,
                                          const float* __restrict__ b1) {
    int cnt = d_cnt;
    int n0 = blockIdx.y * BN;
    __shared__ float Xs[STG][BK][BM];
    __shared__ float Ws[STG][BK][BN];
    __shared__ int tok[BM];
    int tid = threadIdx.x;
    int lxm = tid >> 2, lxk = (tid & 3) << 2;   // X: thread loads rows lxm, cols lxk..+3
    int wr  = tid >> 3, wc  = (tid & 7) << 3;   // W: thread loads row wr, cols wc..+7
    int tm  = tid >> 4, tn  = tid & 15;         // 8x16 thread grid, 4x4 micro

    for (int row0 = blockIdx.x * BM; row0 < cnt; row0 += gridDim.x * BM) {
        __syncthreads();
        if (tid < BM) { int r = row0 + tid; tok[tid] = d_idx[(r < cnt) ? r : cnt - 1]; }
        __syncthreads();
        const float* xr = X + (size_t)tok[lxm] * DIM + lxk;
        const float* wpb = W1 + (size_t)wr * HID + n0 + wc;

        float acc[4][4];
        #pragma unroll
        for (int i = 0; i < 4; i++)
            #pragma unroll
            for (int j = 0; j < 4; j++) acc[i][j] = 0.0f;

        // prologue: issue stages 0..2
        #pragma unroll
        for (int st = 0; st < 3; st++) {
            int k0 = st * BK;
            #pragma unroll
            for (int c = 0; c < 4; c++)
                __pipeline_memcpy_async(&Xs[st][lxk + c][lxm], xr + k0 + c, 4);
            const float* wp = wpb + (size_t)k0 * HID;
            #pragma unroll
            for (int c = 0; c < 8; c++)
                __pipeline_memcpy_async(&Ws[st][wr][wc + c], wp + c, 4);
            __pipeline_commit();
        }

        for (int it = 0; it < DIM / BK; it++) {
            __pipeline_wait_prior(2);   // with empty commits below, stage `it` complete
            __syncthreads();
            int buf = it & (STG - 1);
            #pragma unroll
            for (int k = 0; k < BK; k++) {
                float a[4], bb[4];
                *(float4*)a  = *(const float4*)&Xs[buf][k][tm * 4];   // smem: aligned
                *(float4*)bb = *(const float4*)&Ws[buf][k][tn * 4];
                #pragma unroll
                for (int i = 0; i < 4; i++)
                    #pragma unroll
                    for (int j = 0; j < 4; j++) acc[i][j] += a[i] * bb[j];
            }
            if (it + 3 < DIM / BK) {
                int st = (it + 3) & (STG - 1);
                int k0 = (it + 3) * BK;
                #pragma unroll
                for (int c = 0; c < 4; c++)
                    __pipeline_memcpy_async(&Xs[st][lxk + c][lxm], xr + k0 + c, 4);
                const float* wp = wpb + (size_t)k0 * HID;
                #pragma unroll
                for (int c = 0; c < 8; c++)
                    __pipeline_memcpy_async(&Ws[st][wr][wc + c], wp + c, 4);
            }
            __pipeline_commit();        // commit even when empty: keeps group count exact
        }
        __pipeline_wait_prior(0);

        #pragma unroll
        for (int i = 0; i < 4; i++) {
            int r = row0 + tm * 4 + i;
            if (r < cnt) {
                float o[4];
                #pragma unroll
                for (int j = 0; j < 4; j++) {
                    float h = acc[i][j] + b1[n0 + tn * 4 + j];
                    o[j] = 0.5f * h * (1.0f + erff(h * 0.70710678118654752f));
                }
                *(float4*)&d_H[(size_t)r * HID + n0 + tn * 4] = *(float4*)o;  // own scratch
            }
        }
    }
}

// ---------------- kE: gate + decayed logit for selected tokens ----------------
__global__ void kE(const float* __restrict__ w2, const float* __restrict__ b2,
                   const float* __restrict__ dlam) {
    int cnt = d_cnt;
    int lane = threadIdx.x & 31;
    for (int i = blockIdx.x * 8 + (threadIdx.x >> 5); i < cnt; i += gridDim.x * 8) {
        int t = d_idx[i];
        const float* h = d_H + (size_t)i * HID;
        float z = 0.0f;
        #pragma unroll
        for (int j = 0; j < 16; j++) {          // scalar, warp-contiguous
            int e = lane + j * 32;
            z += h[e] * w2[e];
        }
        z = warp_red(z, false);
        if (lane == 0) {
            float g = 1.0f / (1.0f + expf(-(z + b2[0])));
            d_g[t] = g;
            int b = t >> 11, s = t & (SEQ - 1);
            int L = d_len[b];
            float lam = log1pf(expf(dlam[0]));
            d_dec[t] = g * d_xq[t] * 0.03125f - lam * (float)(L - 1 - s);
        }
    }
}

// ---------------- kF: fused softmax + scene pooling ----------------
// grid (DIM/128, BNUM), 128 threads. Each block recomputes the row softmax
// (deterministic, identical across the 8 d-chunks) then does its weighted sum.
__global__ __launch_bounds__(128) void kF(const float* __restrict__ X,
                                          float* __restrict__ out) {
    __shared__ float w[SEQ];
    __shared__ float red[4];
    __shared__ int slo_s;
    int b = blockIdx.y;
    int tid = threadIdx.x;
    int L = d_len[b];
    if (tid == 0) slo_s = L;

    float v[16];
    float mx = -1e30f;
    #pragma unroll
    for (int i = 0; i < 16; i++) {
        v[i] = d_dec[b * SEQ + tid + i * 128];
        mx = fmaxf(mx, v[i]);
    }
    mx = blk_reduce128(mx, red, true);
    float p[16];
    float sm = 0.0f;
    #pragma unroll
    for (int i = 0; i < 16; i++) {
        p[i] = (v[i] > -1e29f) ? expf(v[i] - mx) : 0.0f;
        sm += p[i];
    }
    sm = blk_reduce128(sm, red, false);
    float inv = 1.0f / sm;
    int slo = L;
    #pragma unroll
    for (int i = 0; i < 16; i++) {
        int s = tid + i * 128;
        float wv = (p[i] > 0.0f) ? p[i] * inv * d_g[b * SEQ + s] : 0.0f;
        w[s] = wv;
        if (wv != 0.0f && s < slo) slo = s;
    }
    atomicMin(&slo_s, slo);
    __syncthreads();

    int d = blockIdx.x * 128 + tid;
    const float* xb = X + (size_t)b * SEQ * DIM + d;
    float a0 = 0.0f, a1 = 0.0f, a2 = 0.0f, a3 = 0.0f;
    int s = slo_s;
    for (; s + 3 < L; s += 4) {
        a0 += w[s + 0] * xb[(size_t)(s + 0) * DIM];
        a1 += w[s + 1] * xb[(size_t)(s + 1) * DIM];
        a2 += w[s + 2] * xb[(size_t)(s + 2) * DIM];
        a3 += w[s + 3] * xb[(size_t)(s + 3) * DIM];
    }
    for (; s < L; s++) a0 += w[s] * xb[(size_t)s * DIM];
    out[b * DIM + d] = (a0 + a1) + (a2 + a3);
}

// ---------------- launch ----------------
extern "C" void kernel_launch(void* const* d_in, const int* in_sizes, int n_in,
                              void* d_out, int out_size) {
    (void)in_sizes; (void)n_in; (void)out_size;
    const float* X    = (const float*)d_in[0];
    const void*  mask = d_in[1];
    const float* gw1  = (const float*)d_in[2];
    const float* gb1  = (const float*)d_in[3];
    const float* gw2  = (const float*)d_in[4];
    const float* gb2  = (const float*)d_in[5];
    const float* dlam = (const float*)d_in[6];
    const float* q    = (const float*)d_in[7];
    const float* kw   = (const float*)d_in[8];
    // d_in[9] = key_b: constant softmax shift, provably drops out
    float* out = (float*)d_out;

    k0d<<<16, 256>>>((const unsigned char*)mask);
    kA <<<32 + DIM, 256>>>(mask, kw, q);
    kB <<<NTOK / 16, 256>>>(X, dlam);
    kD <<<dim3(64, HID / BN), 128>>>(X, gw1, gb1);
    kE <<<128, 256>>>(gw2, gb2, dlam);
    kF <<<dim3(DIM / 128, BNUM), 128>>>(X, out);
}